// round 6
// baseline (speedup 1.0000x reference)
#include <cuda_runtime.h>
#include <cstdint>

#define L_SEQ   1024
#define BATCH   256
#define LB      (L_SEQ*BATCH)
#define KV      10648
#define NFRAG   32
#define KLEN    96
#define ROWS3L  (3*L_SEQ)

typedef unsigned long long ull;

// ---------------- device scratch ----------------
__device__ float4 g_Tk4[KV*16];            // kmer-fused table (10648 x 64)
__device__ float4 g_Ts4[20*16];            // seq-fused table (+b0)
__device__ float  g_ct[(size_t)ROWS3L*BATCH*3];  // c_tilde / frag (in place)
__device__ __align__(16) float g_R[NFRAG*BATCH*12];
__device__ int    g_seq[LB];
__device__ int    g_kmer[LB];
__device__ int    g_flag[2];

// ---------------- f32x2 helpers ----------------
__device__ __forceinline__ ull pk2(float x, float y){
    ull r; asm("mov.b64 %0,{%1,%2};" : "=l"(r) : "f"(x), "f"(y)); return r;
}
__device__ __forceinline__ float2 up2(ull a){
    float x,y; asm("mov.b64 {%0,%1},%2;" : "=f"(x), "=f"(y) : "l"(a));
    return make_float2(x,y);
}
__device__ __forceinline__ ull fma2(ull a, ull b, ull c){
    ull d; asm("fma.rn.f32x2 %0,%1,%2,%3;" : "=l"(d) : "l"(a), "l"(b), "l"(c));
    return d;
}
__device__ __forceinline__ ull add2(ull a, ull b){
    ull d; asm("add.rn.f32x2 %0,%1,%2;" : "=l"(d) : "l"(a), "l"(b));
    return d;
}
__device__ __forceinline__ ull shfl8(ull v, int src){
    unsigned lo = (unsigned)v, hi = (unsigned)(v >> 32);
    lo = __shfl_sync(0xffffffffu, lo, src, 8);
    hi = __shfl_sync(0xffffffffu, hi, src, 8);
    return ((ull)hi << 32) | (ull)lo;
}
__device__ __forceinline__ ull shflx8(ull v, int m){
    unsigned lo = (unsigned)v, hi = (unsigned)(v >> 32);
    lo = __shfl_xor_sync(0xffffffffu, lo, m, 8);
    hi = __shfl_xor_sync(0xffffffffu, hi, m, 8);
    return ((ull)hi << 32) | (ull)lo;
}

// ---------------- dtype detect (int64 vs int32) ----------------
__global__ void k_detect(const int* __restrict__ s, const int* __restrict__ k){
    __shared__ int a0, a1;
    if (threadIdx.x == 0){ a0 = 0; a1 = 0; }
    __syncthreads();
    int a = 0, b = 0;
    for (int i = threadIdx.x; i < 4096; i += 256){ a |= s[2*i+1]; b |= k[2*i+1]; }
    if (a) atomicOr(&a0, 1);
    if (b) atomicOr(&a1, 1);
    __syncthreads();
    if (threadIdx.x == 0){ g_flag[0] = a0 ? 0 : 1; g_flag[1] = a1 ? 0 : 1; }
}
__global__ void k_conv(const int* __restrict__ s, const int* __restrict__ k){
    int f0 = g_flag[0], f1 = g_flag[1];
    for (int i = blockIdx.x*blockDim.x + threadIdx.x; i < LB; i += gridDim.x*blockDim.x){
        g_seq[i]  = f0 ? s[2*i] : s[i];
        g_kmer[i] = f1 ? k[2*i] : k[i];
    }
}

// ---------------- Ts table: seq_embed @ W0[0:16] + b0 ----------------
__global__ void k_ts(const float* __restrict__ se, const float* __restrict__ W0,
                     const float* __restrict__ b0){
    int c = threadIdx.x;
    float* Ts = (float*)g_Ts4;
    for (int s = 0; s < 20; s++){
        float a = b0[c];
        #pragma unroll
        for (int j = 0; j < 16; j++) a += se[s*16+j] * W0[j*64+c];
        Ts[s*64+c] = a;
    }
}

// ---------------- Tk table: kmer_embed @ W0[16:272], 2-phase ----------
__global__ __launch_bounds__(256) void k_tk(const float* __restrict__ ke,
                                            const float* __restrict__ W0){
    extern __shared__ ull smtk[];
    ull* rp  = smtk;          // 16 row-pairs x 256 j = 4096 ull (32KB)
    ull* wt2 = smtk + 4096;   // 64 j-pairs x 128     = 8192 ull (64KB)
    float* rpf = (float*)rp;
    int tid = threadIdx.x;
    int R0 = blockIdx.x * 32;
    for (int i = tid; i < 8192; i += 256){
        int r = i >> 8, j = i & 255;
        int gr = R0 + r;
        float v = (gr < KV) ? ke[(size_t)gr*256 + j] : 0.f;
        rpf[(r>>1)*512 + j*2 + (r&1)] = v;
    }
    int rg = tid >> 6, c = tid & 63;
    ull acc[4];
    #pragma unroll
    for (int pr = 0; pr < 4; pr++) acc[pr] = pk2(0.f, 0.f);
    for (int jt = 0; jt < 2; jt++){
        __syncthreads();
        for (int i = tid; i < 8192; i += 256){
            int j = i >> 6, cc = i & 63;
            float w = W0[(16 + jt*128 + j)*64 + cc];
            wt2[(j>>1)*128 + cc*2 + (j&1)] = pk2(w, w);
        }
        __syncthreads();
        #pragma unroll 4
        for (int j2 = 0; j2 < 64; j2++){
            ulonglong2 w2 = *(const ulonglong2*)(wt2 + j2*128 + (c<<1));
            int jbase = jt*128 + j2*2;
            #pragma unroll
            for (int pr = 0; pr < 4; pr++){
                ulonglong2 r2 = *(const ulonglong2*)(rp + (rg*4+pr)*256 + jbase);
                acc[pr] = fma2(r2.x, w2.x, acc[pr]);
                acc[pr] = fma2(r2.y, w2.y, acc[pr]);
            }
        }
    }
    float* Tk = (float*)g_Tk4;
    #pragma unroll
    for (int pr = 0; pr < 4; pr++){
        int gr = R0 + rg*8 + 2*pr;
        float2 f = up2(acc[pr]);
        if (gr < KV)     Tk[(size_t)gr*64 + c]     = f.x;
        if (gr + 1 < KV) Tk[(size_t)(gr+1)*64 + c] = f.y;
    }
}

// ---------------- main fused MLP (f32x2, register-h, shfl exchange) ----
// 128 thr/block: group g=tid>>3 owns 4 tokens (pairs A,B); lane sub=tid&7
// owns 8 cols [sub*8, sub*8+8). Weights dup-packed, chunk-rotated:
// logical 16B chunk k of lane sub stored at physical chunk (k+(sub>>1))&3.
#define TILES 8
#define OWE 0                          // We: 64 j x 64 ull
#define OW0 4096                       // W0[272:293]: 21 j x 64 ull
#define OW1 5440                       // W1: 64 j x 12 ull (j*12+o)
#define OBE 6208                       // be: 64 ull dup
#define SMEU 6272
#define SME_BYTES (SMEU*8)

__device__ __forceinline__ void mac8(const ull* wr, int sh, ull hjA, ull hjB,
                                     ull* accA, ull* accB){
    #pragma unroll
    for (int k = 0; k < 4; k++){
        int p = ((k + sh) & 3) << 1;
        ulonglong2 ww = *(const ulonglong2*)(wr + p);
        accA[2*k]   = fma2(hjA, ww.x, accA[2*k]);
        accA[2*k+1] = fma2(hjA, ww.y, accA[2*k+1]);
        accB[2*k]   = fma2(hjB, ww.x, accB[2*k]);
        accB[2*k+1] = fma2(hjB, ww.y, accB[2*k+1]);
    }
}

__global__ __launch_bounds__(128,4) void k_mlp(const float* __restrict__ pssm,
        const float* __restrict__ W0, const float* __restrict__ We,
        const float* __restrict__ be, const float* __restrict__ W1,
        const float* __restrict__ b1){
    extern __shared__ ull sm[];
    ull* we2 = sm + OWE;
    ull* w0p = sm + OW0;
    ull* w1p = sm + OW1;
    ull* be2 = sm + OBE;
    __shared__ float b1s[9];
    int tid = threadIdx.x, blk = blockIdx.x;

    // prologue: swizzled dup-packed weights
    #pragma unroll 4
    for (int i = tid; i < 4096; i += 128){
        int j = i >> 6, c = i & 63;
        int sb = c >> 3, i8 = c & 7, k = i8 >> 1;
        int p = (k + (sb >> 1)) & 3;
        float w = We[i];
        we2[j*64 + sb*8 + p*2 + (i8 & 1)] = pk2(w, w);
    }
    for (int i = tid; i < 1344; i += 128){
        int j = i >> 6, c = i & 63;
        int sb = c >> 3, i8 = c & 7, k = i8 >> 1;
        int p = (k + (sb >> 1)) & 3;
        float w = W0[(272+j)*64 + c];
        w0p[j*64 + sb*8 + p*2 + (i8 & 1)] = pk2(w, w);
    }
    for (int i = tid; i < 576; i += 128){
        int j = i/9, o = i - j*9;
        float w = W1[i];
        w1p[j*12 + o] = pk2(w, w);
    }
    if (tid < 64){ float x = be[tid]; be2[tid] = pk2(x, x); }
    if (tid >= 64 && tid < 73) b1s[tid-64] = b1[tid-64];
    __syncthreads();

    int g = tid >> 3, sub = tid & 7;
    int sh = sub >> 1;
    const ull* weL = we2 + sub*8;
    const ull* w0L = w0p + sub*8;

    for (int it = 0; it < TILES; it++){
        int tile = blk*TILES + it;
        int t0 = tile*64 + g*4;
        int4 s4 = *(const int4*)(g_seq + t0);
        int4 k4 = *(const int4*)(g_kmer + t0);

        ull accA[8], accB[8];
        // init from fused tables (own 8 cols, 4 tokens)
        #pragma unroll
        for (int q = 0; q < 2; q++){
            int o = sub*2 + q;
            float4 a0 = g_Tk4[s4.x*0 + k4.x*16 + o];
            float4 a1 = g_Tk4[k4.y*16 + o];
            float4 e0 = g_Ts4[s4.x*16 + o];
            float4 e1 = g_Ts4[s4.y*16 + o];
            accA[q*4+0] = pk2(a0.x+e0.x, a1.x+e1.x);
            accA[q*4+1] = pk2(a0.y+e0.y, a1.y+e1.y);
            accA[q*4+2] = pk2(a0.z+e0.z, a1.z+e1.z);
            accA[q*4+3] = pk2(a0.w+e0.w, a1.w+e1.w);
            float4 c0 = g_Tk4[k4.z*16 + o];
            float4 c1 = g_Tk4[k4.w*16 + o];
            float4 f0 = g_Ts4[s4.z*16 + o];
            float4 f1 = g_Ts4[s4.w*16 + o];
            accB[q*4+0] = pk2(c0.x+f0.x, c1.x+f1.x);
            accB[q*4+1] = pk2(c0.y+f0.y, c1.y+f1.y);
            accB[q*4+2] = pk2(c0.z+f0.z, c1.z+f1.z);
            accB[q*4+3] = pk2(c0.w+f0.w, c1.w+f1.w);
        }
        // pssm @ W0[272:293]
        const float* P0 = pssm + (size_t)t0*21;
        #pragma unroll 3
        for (int j = 0; j < 21; j++){
            ull pjA = pk2(__ldg(P0 + j),      __ldg(P0 + 21 + j));
            ull pjB = pk2(__ldg(P0 + 42 + j), __ldg(P0 + 63 + j));
            mac8(w0L + j*64, sh, pjA, pjB, accA, accB);
        }

        // two relu(h@We+be) layers, register h + width-8 shfl
        #pragma unroll 1
        for (int LL = 0; LL < 2; LL++){
            ull hsA[8], hsB[8];
            #pragma unroll
            for (int i = 0; i < 8; i++){ hsA[i] = accA[i]; hsB[i] = accB[i]; }
            #pragma unroll
            for (int i = 0; i < 8; i++){
                ull bv = be2[sub*8 + i];
                accA[i] = bv; accB[i] = bv;
            }
            #pragma unroll 1
            for (int q = 0; q < 8; q++){
                const ull* wq = weL + q*512;
                #pragma unroll
                for (int jl = 0; jl < 8; jl++){
                    ull hjA = shfl8(hsA[jl], q);
                    ull hjB = shfl8(hsB[jl], q);
                    mac8(wq + jl*64, sh, hjA, hjB, accA, accB);
                }
            }
            #pragma unroll
            for (int i = 0; i < 8; i++){
                float2 fa = up2(accA[i]);
                accA[i] = pk2(fmaxf(fa.x,0.f), fmaxf(fa.y,0.f));
                float2 fb = up2(accB[i]);
                accB[i] = pk2(fmaxf(fb.x,0.f), fmaxf(fb.y,0.f));
            }
        }

        // final 64->9: own 8 j's, butterfly over the 8-lane group
        ull opA[9], opB[9];
        #pragma unroll
        for (int o = 0; o < 9; o++){ opA[o] = 0ull; opB[o] = 0ull; }
        #pragma unroll
        for (int jl = 0; jl < 8; jl++){
            const ull* wr = w1p + (sub*8 + jl)*12;
            ull ha = accA[jl], hb = accB[jl];
            #pragma unroll
            for (int o = 0; o < 9; o++){
                ull w = wr[o];
                opA[o] = fma2(ha, w, opA[o]);
                opB[o] = fma2(hb, w, opB[o]);
            }
        }
        #pragma unroll
        for (int o = 0; o < 9; o++){
            #pragma unroll
            for (int m = 1; m < 8; m <<= 1){
                opA[o] = add2(opA[o], shflx8(opA[o], m));
                opB[o] = add2(opB[o], shflx8(opB[o], m));
            }
        }
        if (sub < 4){
            int t = t0 + sub;
            int l = t >> 8, bb = t & 255;
            #pragma unroll
            for (int o = 0; o < 9; o++){
                float2 va = up2(opA[o]), vb = up2(opB[o]);
                float val = (sub == 0) ? va.x : (sub == 1) ? va.y
                          : (sub == 2) ? vb.x : vb.y;
                val += b1s[o];
                int r = o/3, j3 = o - r*3;
                g_ct[((size_t)(3*l + r)*256 + bb)*3 + j3] = val;
            }
        }
    }
}

// ---------------- fragment NeRF scan (in place over g_ct) ----------------
__global__ __launch_bounds__(256) void k_frag(){
    int tid = blockIdx.x*256 + threadIdx.x;
    int b = tid & 255, f = tid >> 8;
    float pax = -0.70710678118654752f, pay = 1.22474487139158905f, paz = 0.f;
    float pbx = -1.41421356237309505f, pby = 0.f, pbz = 0.f;
    float pcx = 0.f, pcy = 0.f, pcz = 0.f;
    float nx[2], ny[2], nz[2];
    #pragma unroll
    for (int q = 0; q < 2; q++){
        size_t id = ((size_t)(f*KLEN + q)*256 + b)*3;
        nx[q] = g_ct[id]; ny[q] = g_ct[id+1]; nz[q] = g_ct[id+2];
    }
    #pragma unroll 1
    for (int t = 0; t < KLEN; t++){
        float tx = nx[0], ty = ny[0], tz = nz[0];
        nx[0] = nx[1]; ny[0] = ny[1]; nz[0] = nz[1];
        if (t + 2 < KLEN){
            size_t id = ((size_t)(f*KLEN + t + 2)*256 + b)*3;
            nx[1] = g_ct[id]; ny[1] = g_ct[id+1]; nz[1] = g_ct[id+2];
        }
        float ux = pcx-pbx, uy = pcy-pby, uz = pcz-pbz;
        float s = rsqrtf(fmaxf(ux*ux+uy*uy+uz*uz, 1e-24f));
        ux *= s; uy *= s; uz *= s;
        float vx = pbx-pax, vy = pby-pay, vz = pbz-paz;
        float wx = vy*uz - vz*uy, wy = vz*ux - vx*uz, wz = vx*uy - vy*ux;
        float s2 = rsqrtf(fmaxf(wx*wx+wy*wy+wz*wz, 1e-24f));
        wx *= s2; wy *= s2; wz *= s2;
        float mx = wy*uz - wz*uy, my = wz*ux - wx*uz, mz = wx*uy - wy*ux;
        float dx = pcx + ux*tx + mx*ty + wx*tz;
        float dy = pcy + uy*tx + my*ty + wy*tz;
        float dz = pcz + uz*tx + mz*ty + wz*tz;
        size_t od = ((size_t)(f*KLEN + t)*256 + b)*3;
        g_ct[od] = dx; g_ct[od+1] = dy; g_ct[od+2] = dz;
        pax = pbx; pay = pby; paz = pbz;
        pbx = pcx; pby = pcy; pbz = pcz;
        pcx = dx;  pcy = dy;  pcz = dz;
    }
}

// ---------------- assembly carry chain ----------------
__global__ void k_carry(){
    int b = threadIdx.x;
    float pax = -0.70710678118654752f, pay = 1.22474487139158905f, paz = 0.f;
    float pbx = -1.41421356237309505f, pby = 0.f, pbz = 0.f;
    float pcx = 0.f, pcy = 0.f, pcz = 0.f;
    for (int f = 0; f < NFRAG; f++){
        float ux = pcx-pbx, uy = pcy-pby, uz = pcz-pbz;
        float s = rsqrtf(fmaxf(ux*ux+uy*uy+uz*uz, 1e-24f));
        ux *= s; uy *= s; uz *= s;
        float vx = pbx-pax, vy = pby-pay, vz = pbz-paz;
        float wx = vy*uz - vz*uy, wy = vz*ux - vx*uz, wz = vx*uy - vy*ux;
        float s2 = rsqrtf(fmaxf(wx*wx+wy*wy+wz*wz, 1e-24f));
        wx *= s2; wy *= s2; wz *= s2;
        float mx = wy*uz - wz*uy, my = wz*ux - wx*uz, mz = wx*uy - wy*ux;
        float* R = g_R + ((size_t)f*256 + b)*12;
        R[0]=ux; R[1]=uy; R[2]=uz;
        R[3]=mx; R[4]=my; R[5]=mz;
        R[6]=wx; R[7]=wy; R[8]=wz;
        R[9]=pcx; R[10]=pcy; R[11]=pcz;
        float yx[3], yy[3], yz[3];
        #pragma unroll
        for (int i = 0; i < 3; i++){
            size_t id = ((size_t)(f*KLEN + 93 + i)*256 + b)*3;
            float px = g_ct[id], py = g_ct[id+1], pz = g_ct[id+2];
            yx[i] = pcx + ux*px + mx*py + wx*pz;
            yy[i] = pcy + uy*px + my*py + wy*pz;
            yz[i] = pcz + uz*px + mz*py + wz*pz;
        }
        pax = yx[0]; pay = yy[0]; paz = yz[0];
        pbx = yx[1]; pby = yy[1]; pbz = yz[1];
        pcx = yx[2]; pcy = yy[2]; pcz = yz[2];
    }
}

// ---------------- apply rigid transforms ----------------
__global__ __launch_bounds__(256) void k_apply(float* __restrict__ out){
    int t = blockIdx.x;
    int f = blockIdx.y;
    int b = threadIdx.x;
    const float4* R4 = (const float4*)g_R;
    float4 q0 = R4[(f*256 + b)*3 + 0];
    float4 q1 = R4[(f*256 + b)*3 + 1];
    float4 q2 = R4[(f*256 + b)*3 + 2];
    size_t id = ((size_t)(f*KLEN + t)*256 + b)*3;
    float px = g_ct[id], py = g_ct[id+1], pz = g_ct[id+2];
    out[id]   = q2.y + q0.x*px + q0.w*py + q1.z*pz;
    out[id+1] = q2.z + q0.y*px + q1.x*py + q1.w*pz;
    out[id+2] = q2.w + q0.z*px + q1.y*py + q2.x*pz;
}

extern "C" void kernel_launch(void* const* d_in, const int* in_sizes, int n_in,
                              void* d_out, int out_size){
    const int*   seq  = (const int*)d_in[0];
    const int*   kmer = (const int*)d_in[1];
    const float* pssm = (const float*)d_in[2];
    const float* se   = (const float*)d_in[4];
    const float* ke   = (const float*)d_in[5];
    const float* W0   = (const float*)d_in[6];
    const float* b0   = (const float*)d_in[7];
    const float* We   = (const float*)d_in[8];
    const float* be   = (const float*)d_in[9];
    const float* W1   = (const float*)d_in[10];
    const float* b1   = (const float*)d_in[11];

    cudaFuncSetAttribute(k_mlp, cudaFuncAttributeMaxDynamicSharedMemorySize, SME_BYTES);
    cudaFuncSetAttribute(k_tk,  cudaFuncAttributeMaxDynamicSharedMemorySize, 98304);

    k_detect<<<1,256>>>(seq, kmer);
    k_conv<<<264,256>>>(seq, kmer);
    k_ts<<<1,64>>>(se, W0, b0);
    k_tk<<<(KV+31)/32,256,98304>>>(ke, W0);
    k_mlp<<<512,128,SME_BYTES>>>(pssm, W0, We, be, W1, b1);
    k_frag<<<32,256>>>();
    k_carry<<<1,256>>>();
    dim3 ga(96, 32);
    k_apply<<<ga,256>>>((float*)d_out);
}

// round 7
// speedup vs baseline: 1.6864x; 1.6864x over previous
#include <cuda_runtime.h>
#include <cstdint>

#define L_SEQ   1024
#define BATCH   256
#define LB      (L_SEQ*BATCH)
#define KV      10648
#define NFRAG   32
#define KLEN    96
#define ROWS3L  (3*L_SEQ)

typedef unsigned long long ull;

// ---------------- device scratch ----------------
__device__ float4 g_Tk4[KV*16];            // kmer-fused table (10648 x 64)
__device__ float4 g_Ts4[20*16];            // seq-fused table (+b0)
__device__ float  g_ct[(size_t)ROWS3L*BATCH*3];  // c_tilde / frag (in place)
__device__ __align__(16) float g_R[NFRAG*BATCH*12];
__device__ int    g_seq[LB];
__device__ int    g_kmer[LB];
__device__ int    g_flag[2];

// ---------------- f32x2 helpers ----------------
__device__ __forceinline__ ull pk2(float x, float y){
    ull r; asm("mov.b64 %0,{%1,%2};" : "=l"(r) : "f"(x), "f"(y)); return r;
}
__device__ __forceinline__ float2 up2(ull a){
    float x,y; asm("mov.b64 {%0,%1},%2;" : "=f"(x), "=f"(y) : "l"(a));
    return make_float2(x,y);
}
__device__ __forceinline__ ull fma2(ull a, ull b, ull c){
    ull d; asm("fma.rn.f32x2 %0,%1,%2,%3;" : "=l"(d) : "l"(a), "l"(b), "l"(c));
    return d;
}
__device__ __forceinline__ ull relu2(ull a){
    float2 f = up2(a);
    return pk2(fmaxf(f.x, 0.f), fmaxf(f.y, 0.f));
}
__device__ __forceinline__ ull shfl2(ull v, int src){
    unsigned lo = (unsigned)v, hi = (unsigned)(v >> 32);
    lo = __shfl_sync(0xffffffffu, lo, src, 2);
    hi = __shfl_sync(0xffffffffu, hi, src, 2);
    return ((ull)hi << 32) | (ull)lo;
}

// ---------------- dtype detect (int64 vs int32) ----------------
__global__ void k_detect(const int* __restrict__ s, const int* __restrict__ k){
    __shared__ int a0, a1;
    if (threadIdx.x == 0){ a0 = 0; a1 = 0; }
    __syncthreads();
    int a = 0, b = 0;
    for (int i = threadIdx.x; i < 4096; i += 256){ a |= s[2*i+1]; b |= k[2*i+1]; }
    if (a) atomicOr(&a0, 1);
    if (b) atomicOr(&a1, 1);
    __syncthreads();
    if (threadIdx.x == 0){ g_flag[0] = a0 ? 0 : 1; g_flag[1] = a1 ? 0 : 1; }
}
__global__ void k_conv(const int* __restrict__ s, const int* __restrict__ k){
    int f0 = g_flag[0], f1 = g_flag[1];
    for (int i = blockIdx.x*blockDim.x + threadIdx.x; i < LB; i += gridDim.x*blockDim.x){
        g_seq[i]  = f0 ? s[2*i] : s[i];
        g_kmer[i] = f1 ? k[2*i] : k[i];
    }
}

// ---------------- Ts table: seq_embed @ W0[0:16] + b0 ----------------
__global__ void k_ts(const float* __restrict__ se, const float* __restrict__ W0,
                     const float* __restrict__ b0){
    int c = threadIdx.x;
    float* Ts = (float*)g_Ts4;
    for (int s = 0; s < 20; s++){
        float a = b0[c];
        #pragma unroll
        for (int j = 0; j < 16; j++) a += se[s*16+j] * W0[j*64+c];
        Ts[s*64+c] = a;
    }
}

// ---------------- Tk table: row-per-thread, broadcast weights ----------
// W0[16:272] (256 x 64) staged in 64KB smem as col-pair f32x2 rows; every
// lane reads the same row per k -> pure broadcast LDS. ke streamed float4.
__global__ __launch_bounds__(128) void k_tk(const float* __restrict__ ke,
                                            const float* __restrict__ W0){
    extern __shared__ ull w0k[];           // 8192 ull = 64KB, [k][32 col-pairs]
    float* w0f = (float*)w0k;
    int tid = threadIdx.x;
    for (int i = tid; i < 16384; i += 128) w0f[i] = W0[1024 + i];
    __syncthreads();
    int r = blockIdx.x*128 + tid;
    if (r >= KV) return;

    ull acc[32];
    #pragma unroll
    for (int kk = 0; kk < 32; kk++) acc[kk] = 0ull;

    const float4* kr = (const float4*)(ke + (size_t)r*256);
    #pragma unroll 2
    for (int k4 = 0; k4 < 64; k4++){
        float4 kv = __ldg(kr + k4);
        float sv[4] = {kv.x, kv.y, kv.z, kv.w};
        #pragma unroll
        for (int e = 0; e < 4; e++){
            ull hj = pk2(sv[e], sv[e]);
            const ull* wr = w0k + (k4*4 + e)*32;
            #pragma unroll
            for (int k2 = 0; k2 < 16; k2++){
                ulonglong2 ww = *(const ulonglong2*)(wr + 2*k2);
                acc[2*k2]   = fma2(hj, ww.x, acc[2*k2]);
                acc[2*k2+1] = fma2(hj, ww.y, acc[2*k2+1]);
            }
        }
    }
    float2* dst = (float2*)((float*)g_Tk4 + (size_t)r*64);
    #pragma unroll
    for (int kk = 0; kk < 32; kk++) dst[kk] = up2(acc[kk]);
}

// ---------------- main fused MLP (col-pair f32x2, register h) ----------
// 128 thr/block, 2 chunks of 128 tokens. Lane pair p=(lane>>1) owns tokens
// (tA,tB); halfc=lane&1 owns cols [halfc*32, +32) as 16 f32x2 col-pairs.
// Weights undup'd col-pair packed, skew 18-ull between halves (bank split).
#define SWR 36
__global__ __launch_bounds__(128,3) void k_mlp(const float* __restrict__ pssm,
        const float* __restrict__ W0, const float* __restrict__ We,
        const float* __restrict__ be, const float* __restrict__ W1,
        const float* __restrict__ b1){
    __shared__ ull we2[64*SWR];    // [j][half*18 + kk]
    __shared__ ull w0p[21*SWR];
    __shared__ ull w1p[324];       // [halfc*162 + kk*10 + o]
    __shared__ ull bep[36];
    __shared__ float b1s[9];
    int tid = threadIdx.x, blk = blockIdx.x;

    // prologue
    for (int i = tid; i < 4096; i += 128){
        int j = i >> 6, c = i & 63;
        int half = c >> 5, kk = (c & 31) >> 1, comp = c & 1;
        ((float*)we2)[(j*SWR + half*18 + kk)*2 + comp] = We[i];
    }
    for (int i = tid; i < 1344; i += 128){
        int j = i >> 6, c = i & 63;
        int half = c >> 5, kk = (c & 31) >> 1, comp = c & 1;
        ((float*)w0p)[(j*SWR + half*18 + kk)*2 + comp] = W0[(272+j)*64 + c];
    }
    for (int i = tid; i < 576; i += 128){
        int j = i/9, o = i - j*9;
        int gk = j >> 1, comp = j & 1;
        ((float*)w1p)[((gk>>4)*162 + (gk&15)*10 + o)*2 + comp] = W1[i];
    }
    if (tid < 32){
        int half = tid >> 4, kk = tid & 15;
        bep[half*18 + kk] = pk2(be[half*32 + 2*kk], be[half*32 + 2*kk + 1]);
    }
    if (tid >= 32 && tid < 41) b1s[tid-32] = b1[tid-32];
    __syncthreads();

    int lane = tid & 31, w = tid >> 5;
    int pI = lane >> 1, halfc = lane & 1;
    int myoff = halfc*18;

    for (int ch = 0; ch < 2; ch++){
        int base = blk*256 + ch*128 + w*32;
        int tA = base + 2*pI, tB = tA + 1;
        int sA = g_seq[tA], sB = g_seq[tB];
        int kA = g_kmer[tA], kB = g_kmer[tB];

        ull accA[16], accB[16], hA[16], hB[16];
        // layer0 init from fused tables (own half cols)
        #pragma unroll
        for (int q = 0; q < 8; q++){
            float4 ka = g_Tk4[kA*16 + (halfc<<3) + q];
            float4 ea = g_Ts4[sA*16 + (halfc<<3) + q];
            accA[2*q]   = pk2(ka.x+ea.x, ka.y+ea.y);
            accA[2*q+1] = pk2(ka.z+ea.z, ka.w+ea.w);
            float4 kb = g_Tk4[kB*16 + (halfc<<3) + q];
            float4 eb = g_Ts4[sB*16 + (halfc<<3) + q];
            accB[2*q]   = pk2(kb.x+eb.x, kb.y+eb.y);
            accB[2*q+1] = pk2(kb.z+eb.z, kb.w+eb.w);
        }
        // pssm @ W0[272:293]
        const float* PA = pssm + (size_t)tA*21;
        const float* PB = pssm + (size_t)tB*21;
        #pragma unroll 3
        for (int j = 0; j < 21; j++){
            float pa = __ldg(PA + j), pb = __ldg(PB + j);
            ull hjA = pk2(pa, pa), hjB = pk2(pb, pb);
            const ull* wr = w0p + j*SWR + myoff;
            #pragma unroll
            for (int k2 = 0; k2 < 8; k2++){
                ulonglong2 ww = *(const ulonglong2*)(wr + 2*k2);
                accA[2*k2]   = fma2(hjA, ww.x, accA[2*k2]);
                accA[2*k2+1] = fma2(hjA, ww.y, accA[2*k2+1]);
                accB[2*k2]   = fma2(hjB, ww.x, accB[2*k2]);
                accB[2*k2+1] = fma2(hjB, ww.y, accB[2*k2+1]);
            }
        }
        #pragma unroll
        for (int kk = 0; kk < 16; kk++){ hA[kk] = accA[kk]; hB[kk] = accB[kk]; }

        // two relu(h @ We + be) layers
        #pragma unroll 1
        for (int LL = 0; LL < 2; LL++){
            #pragma unroll
            for (int kk = 0; kk < 16; kk++){
                ull bv = bep[myoff + kk];
                accA[kk] = bv; accB[kk] = bv;
            }
            #pragma unroll
            for (int kk = 0; kk < 16; kk++){
                #pragma unroll
                for (int ow = 0; ow < 2; ow++){
                    ull vA = shfl2(hA[kk], ow);
                    ull vB = shfl2(hB[kk], ow);
                    #pragma unroll
                    for (int comp = 0; comp < 2; comp++){
                        int j = ow*32 + kk*2 + comp;
                        float2 fa = up2(vA); float sa = comp ? fa.y : fa.x;
                        float2 fb = up2(vB); float sb = comp ? fb.y : fb.x;
                        ull hjA = pk2(sa, sa), hjB = pk2(sb, sb);
                        const ull* wr = we2 + j*SWR + myoff;
                        #pragma unroll
                        for (int k2 = 0; k2 < 8; k2++){
                            ulonglong2 ww = *(const ulonglong2*)(wr + 2*k2);
                            accA[2*k2]   = fma2(hjA, ww.x, accA[2*k2]);
                            accA[2*k2+1] = fma2(hjA, ww.y, accA[2*k2+1]);
                            accB[2*k2]   = fma2(hjB, ww.x, accB[2*k2]);
                            accB[2*k2+1] = fma2(hjB, ww.y, accB[2*k2+1]);
                        }
                    }
                }
            }
            #pragma unroll
            for (int kk = 0; kk < 16; kk++){
                hA[kk] = relu2(accA[kk]);
                hB[kk] = relu2(accB[kk]);
            }
        }

        // final 64->9: partial over own half, combine across lane pair
        ull opA[9], opB[9];
        #pragma unroll
        for (int o = 0; o < 9; o++){ opA[o] = 0ull; opB[o] = 0ull; }
        #pragma unroll
        for (int kk = 0; kk < 16; kk++){
            const ull* wr = w1p + halfc*162 + kk*10;
            ull ha = hA[kk], hb = hB[kk];
            #pragma unroll
            for (int o = 0; o < 9; o++){
                ull ww = wr[o];
                opA[o] = fma2(ha, ww, opA[o]);
                opB[o] = fma2(hb, ww, opB[o]);
            }
        }
        int t = halfc ? tB : tA;
        int l = t >> 8, bb = t & 255;
        #pragma unroll
        for (int o = 0; o < 9; o++){
            float2 fa = up2(opA[o]); float va = fa.x + fa.y;
            va += __shfl_xor_sync(0xffffffffu, va, 1);
            float2 fb = up2(opB[o]); float vb = fb.x + fb.y;
            vb += __shfl_xor_sync(0xffffffffu, vb, 1);
            float v = (halfc ? vb : va) + b1s[o];
            int r = o/3, j3 = o - r*3;
            g_ct[((size_t)(3*l + r)*256 + bb)*3 + j3] = v;
        }
    }
}

// ---------------- fragment NeRF scan (in place over g_ct) ----------------
__global__ __launch_bounds__(256) void k_frag(){
    int tid = blockIdx.x*256 + threadIdx.x;
    int b = tid & 255, f = tid >> 8;
    float pax = -0.70710678118654752f, pay = 1.22474487139158905f, paz = 0.f;
    float pbx = -1.41421356237309505f, pby = 0.f, pbz = 0.f;
    float pcx = 0.f, pcy = 0.f, pcz = 0.f;
    float nx[2], ny[2], nz[2];
    #pragma unroll
    for (int q = 0; q < 2; q++){
        size_t id = ((size_t)(f*KLEN + q)*256 + b)*3;
        nx[q] = g_ct[id]; ny[q] = g_ct[id+1]; nz[q] = g_ct[id+2];
    }
    #pragma unroll 1
    for (int t = 0; t < KLEN; t++){
        float tx = nx[0], ty = ny[0], tz = nz[0];
        nx[0] = nx[1]; ny[0] = ny[1]; nz[0] = nz[1];
        if (t + 2 < KLEN){
            size_t id = ((size_t)(f*KLEN + t + 2)*256 + b)*3;
            nx[1] = g_ct[id]; ny[1] = g_ct[id+1]; nz[1] = g_ct[id+2];
        }
        float ux = pcx-pbx, uy = pcy-pby, uz = pcz-pbz;
        float s = rsqrtf(fmaxf(ux*ux+uy*uy+uz*uz, 1e-24f));
        ux *= s; uy *= s; uz *= s;
        float vx = pbx-pax, vy = pby-pay, vz = pbz-paz;
        float wx = vy*uz - vz*uy, wy = vz*ux - vx*uz, wz = vx*uy - vy*ux;
        float s2 = rsqrtf(fmaxf(wx*wx+wy*wy+wz*wz, 1e-24f));
        wx *= s2; wy *= s2; wz *= s2;
        float mx = wy*uz - wz*uy, my = wz*ux - wx*uz, mz = wx*uy - wy*ux;
        float dx = pcx + ux*tx + mx*ty + wx*tz;
        float dy = pcy + uy*tx + my*ty + wy*tz;
        float dz = pcz + uz*tx + mz*ty + wz*tz;
        size_t od = ((size_t)(f*KLEN + t)*256 + b)*3;
        g_ct[od] = dx; g_ct[od+1] = dy; g_ct[od+2] = dz;
        pax = pbx; pay = pby; paz = pbz;
        pbx = pcx; pby = pcy; pbz = pcz;
        pcx = dx;  pcy = dy;  pcz = dz;
    }
}

// ---------------- assembly carry chain ----------------
__global__ void k_carry(){
    int b = threadIdx.x;
    float pax = -0.70710678118654752f, pay = 1.22474487139158905f, paz = 0.f;
    float pbx = -1.41421356237309505f, pby = 0.f, pbz = 0.f;
    float pcx = 0.f, pcy = 0.f, pcz = 0.f;
    for (int f = 0; f < NFRAG; f++){
        float ux = pcx-pbx, uy = pcy-pby, uz = pcz-pbz;
        float s = rsqrtf(fmaxf(ux*ux+uy*uy+uz*uz, 1e-24f));
        ux *= s; uy *= s; uz *= s;
        float vx = pbx-pax, vy = pby-pay, vz = pbz-paz;
        float wx = vy*uz - vz*uy, wy = vz*ux - vx*uz, wz = vx*uy - vy*ux;
        float s2 = rsqrtf(fmaxf(wx*wx+wy*wy+wz*wz, 1e-24f));
        wx *= s2; wy *= s2; wz *= s2;
        float mx = wy*uz - wz*uy, my = wz*ux - wx*uz, mz = wx*uy - wy*ux;
        float* R = g_R + ((size_t)f*256 + b)*12;
        R[0]=ux; R[1]=uy; R[2]=uz;
        R[3]=mx; R[4]=my; R[5]=mz;
        R[6]=wx; R[7]=wy; R[8]=wz;
        R[9]=pcx; R[10]=pcy; R[11]=pcz;
        float yx[3], yy[3], yz[3];
        #pragma unroll
        for (int i = 0; i < 3; i++){
            size_t id = ((size_t)(f*KLEN + 93 + i)*256 + b)*3;
            float px = g_ct[id], py = g_ct[id+1], pz = g_ct[id+2];
            yx[i] = pcx + ux*px + mx*py + wx*pz;
            yy[i] = pcy + uy*px + my*py + wy*pz;
            yz[i] = pcz + uz*px + mz*py + wz*pz;
        }
        pax = yx[0]; pay = yy[0]; paz = yz[0];
        pbx = yx[1]; pby = yy[1]; pbz = yz[1];
        pcx = yx[2]; pcy = yy[2]; pcz = yz[2];
    }
}

// ---------------- apply rigid transforms ----------------
__global__ __launch_bounds__(256) void k_apply(float* __restrict__ out){
    int t = blockIdx.x;
    int f = blockIdx.y;
    int b = threadIdx.x;
    const float4* R4 = (const float4*)g_R;
    float4 q0 = R4[(f*256 + b)*3 + 0];
    float4 q1 = R4[(f*256 + b)*3 + 1];
    float4 q2 = R4[(f*256 + b)*3 + 2];
    size_t id = ((size_t)(f*KLEN + t)*256 + b)*3;
    float px = g_ct[id], py = g_ct[id+1], pz = g_ct[id+2];
    out[id]   = q2.y + q0.x*px + q0.w*py + q1.z*pz;
    out[id+1] = q2.z + q0.y*px + q1.x*py + q1.w*pz;
    out[id+2] = q2.w + q0.z*px + q1.y*py + q2.x*pz;
}

extern "C" void kernel_launch(void* const* d_in, const int* in_sizes, int n_in,
                              void* d_out, int out_size){
    const int*   seq  = (const int*)d_in[0];
    const int*   kmer = (const int*)d_in[1];
    const float* pssm = (const float*)d_in[2];
    const float* se   = (const float*)d_in[4];
    const float* ke   = (const float*)d_in[5];
    const float* W0   = (const float*)d_in[6];
    const float* b0   = (const float*)d_in[7];
    const float* We   = (const float*)d_in[8];
    const float* be   = (const float*)d_in[9];
    const float* W1   = (const float*)d_in[10];
    const float* b1   = (const float*)d_in[11];

    cudaFuncSetAttribute(k_tk, cudaFuncAttributeMaxDynamicSharedMemorySize, 65536);

    k_detect<<<1,256>>>(seq, kmer);
    k_conv<<<264,256>>>(seq, kmer);
    k_ts<<<1,64>>>(se, W0, b0);
    k_tk<<<(KV+127)/128,128,65536>>>(ke, W0);
    k_mlp<<<LB/256,128>>>(pssm, W0, We, be, W1, b1);
    k_frag<<<32,256>>>();
    k_carry<<<1,256>>>();
    dim3 ga(96, 32);
    k_apply<<<ga,256>>>((float*)d_out);
}